// round 16
// baseline (speedup 1.0000x reference)
#include <cuda_runtime.h>
#include <cuda_fp16.h>
#include <cstdint>

#define D      512
#define NB     512       // context rows (B)
#define NM     65536     // memory rows (M)
#define BM     128       // m rows per CTA tile
#define BN     128       // b cols per CTA tile
#define BK     64        // k per pipeline stage
#define NMT    (NM / BM) // 512 m-tiles
#define NSUB   (NM / 32) // 2048 sub-blocks of 32 rows
#define NKS    (D / BK)  // 8 k stages
#define NSTAGE 3
#define LDA    72        // padded smem row stride (elems) -> conflict-free ldmatrix
#define STAGE_E (BM * LDA)            // elems per operand per stage (9216)
#define STAGE_B (STAGE_E * 2)         // bytes (18432)
#define MARGIN 0.0025f   // > 2x (fp16 dot err 2^-10 + fp32 accum err ~3e-5)

// ---------------- device scratch (no cudaMalloc allowed) ----------------
__device__ float   g_ctxn[NB * D];           // normalized ctx fp32 (exact rescore)
__device__ __half  g_ctxh[NB * D];           // normalized ctx fp16
__device__ __half  g_memh[(size_t)NM * D];   // normalized mem fp16 (64MB)
__device__ float   g_minv[NM];
__device__ float   g_submax[(size_t)NB * NSUB];  // [b][sub] 4MB
__device__ int     g_arrive[NMT];            // per-m-tile conversion arrival count

// ---------------- ctx: normalize -> fp32 + fp16; resets arrival counters ----------------
__global__ void ctx_prep_kernel(const float* __restrict__ ctx) {
    const int b = blockIdx.x;
    const int t = threadIdx.x;                     // 128 threads, one float4 each
    if (t == 0) g_arrive[b] = 0;                   // NB == NMT == 512
    float4 v = ((const float4*)(ctx + (size_t)b * D))[t];
    float ss = v.x * v.x + v.y * v.y + v.z * v.z + v.w * v.w;
    #pragma unroll
    for (int o = 16; o; o >>= 1) ss += __shfl_xor_sync(0xffffffffu, ss, o);
    __shared__ float ws[4];
    if ((t & 31) == 0) ws[t >> 5] = ss;
    __syncthreads();
    float sc = rsqrtf(fmaxf(ws[0] + ws[1] + ws[2] + ws[3], 1e-12f));
    float4 n4 = make_float4(v.x * sc, v.y * sc, v.z * sc, v.w * sc);
    ((float4*)(g_ctxn + (size_t)b * D))[t] = n4;
    __half2 p0 = __floats2half2_rn(n4.x, n4.y);
    __half2 p1 = __floats2half2_rn(n4.z, n4.w);
    uint2 u = make_uint2(*(uint32_t*)&p0, *(uint32_t*)&p1);
    *(uint2*)(g_ctxh + (size_t)b * D + 4 * t) = u;
}

// ---------------- asm helpers ----------------
__device__ __forceinline__ uint32_t smem_u32(const void* p) {
    uint32_t a;
    asm("{ .reg .u64 t; cvta.to.shared.u64 t, %1; cvt.u32.u64 %0, t; }" : "=r"(a) : "l"(p));
    return a;
}
__device__ __forceinline__ void cpa16(uint32_t dst, const void* src) {
    asm volatile("cp.async.cg.shared.global [%0], [%1], 16;" :: "r"(dst), "l"(src));
}
__device__ __forceinline__ void cpa_commit() {
    asm volatile("cp.async.commit_group;");
}
__device__ __forceinline__ void cpa_wait1() {
    asm volatile("cp.async.wait_group 1;");
}
__device__ __forceinline__ void ldsm_x4(uint32_t& r0, uint32_t& r1, uint32_t& r2, uint32_t& r3,
                                        uint32_t addr) {
    asm volatile("ldmatrix.sync.aligned.m8n8.x4.shared.b16 {%0,%1,%2,%3}, [%4];"
                 : "=r"(r0), "=r"(r1), "=r"(r2), "=r"(r3) : "r"(addr));
}
__device__ __forceinline__ void hmma(float* c, const uint32_t* a, uint32_t b0, uint32_t b1) {
    asm volatile(
        "mma.sync.aligned.m16n8k16.row.col.f32.f16.f16.f32 "
        "{%0,%1,%2,%3}, {%4,%5,%6,%7}, {%8,%9}, {%0,%1,%2,%3};"
        : "+f"(c[0]), "+f"(c[1]), "+f"(c[2]), "+f"(c[3])
        : "r"(a[0]), "r"(a[1]), "r"(a[2]), "r"(a[3]), "r"(b0), "r"(b1));
}
__device__ __forceinline__ int ld_acquire(const int* p) {
    int v;
    asm volatile("ld.acquire.gpu.global.b32 %0, [%1];" : "=r"(v) : "l"(p) : "memory");
    return v;
}

// ---------------- inline conversion: 32 rows of one m-tile (noinline: protect regs) ----------------
__device__ __noinline__ void convert_quarter(const float* __restrict__ memf, int row0,
                                             int wid, int lane) {
    #pragma unroll 1
    for (int i = 0; i < 4; i++) {                  // 8 warps x 4 rows = 32 rows
        const int m = row0 + wid * 4 + i;
        const float4* row = (const float4*)(memf + (size_t)m * D);
        float4 v[4];
        float ss = 0.f;
        #pragma unroll
        for (int j = 0; j < 4; j++) {
            v[j] = row[lane + 32 * j];
            ss += v[j].x * v[j].x + v[j].y * v[j].y + v[j].z * v[j].z + v[j].w * v[j].w;
        }
        #pragma unroll
        for (int o = 16; o; o >>= 1) ss += __shfl_xor_sync(0xffffffffu, ss, o);
        float inv = rsqrtf(fmaxf(ss, 1e-12f));
        if (lane == 0) g_minv[m] = inv;
        #pragma unroll
        for (int j = 0; j < 4; j++) {
            __half2 p0 = __floats2half2_rn(v[j].x * inv, v[j].y * inv);
            __half2 p1 = __floats2half2_rn(v[j].z * inv, v[j].w * inv);
            uint2 u = make_uint2(*(uint32_t*)&p0, *(uint32_t*)&p1);
            *(uint2*)(g_memh + (size_t)m * D + 4 * (lane + 32 * j)) = u;
        }
    }
}

// ---------------- phase 1: inline convert + fp16 GEMM + per-(b, 32-row-sub) max ----------------
// CTA: 128 m x 128 b, 256 threads (8 warps: 4 m-warps (wm) x 2 n-warps (wn)).
// The 4 sibling CTAs of an m-tile (b-blocks 0..3, adjacent bids) each convert one
// 32-row quarter, then rendezvous on g_arrive[mblk] before consuming the fp16 tile.
#define SMEM_RED (NSTAGE * 2 * STAGE_B)        // 110592: after 3 stages of A+B
#define SMEM_TOT (SMEM_RED + BN * 4 * 4)       // + sred2[128][4] floats = 112640

__global__ __launch_bounds__(256, 2) void score_gemm_kernel(const float* __restrict__ memf) {
    extern __shared__ char sm[];
    const uint32_t smb = smem_u32(sm);
    const int tid  = threadIdx.x;
    const int lane = tid & 31;
    const int wid  = tid >> 5;
    const int wm   = wid & 3;
    const int wn   = wid >> 2;
    const int b0   = blockIdx.x * BN;
    const int mblk = blockIdx.y;
    const int m0   = mblk * BM;

    // ---- cooperative conversion: this CTA's quarter of the shared m-tile ----
    convert_quarter(memf, m0 + blockIdx.x * 32, wid, lane);
    __threadfence();                               // each thread's stores visible
    __syncthreads();                               // all threads fenced
    if (tid == 0) {
        atomicAdd(&g_arrive[mblk], 1);
        while (ld_acquire(&g_arrive[mblk]) < 4) __nanosleep(64);
    }
    __syncthreads();                               // full fp16 m-tile ready

    auto load_stage = [&](int ks) {
        const int st = ks % NSTAGE;
        const uint32_t aB = smb + st * (2 * STAGE_B);
        const uint32_t bB = aB + STAGE_B;
        const __half* gA = g_memh + (size_t)m0 * D + ks * BK;
        const __half* gB = g_ctxh + (size_t)b0 * D + ks * BK;
        #pragma unroll
        for (int it = 0; it < 4; it++) {
            int f = tid + it * 256;
            int r = f >> 3, c = (f & 7) << 3;
            cpa16(aB + (r * LDA + c) * 2, gA + (size_t)r * D + c);
            cpa16(bB + (r * LDA + c) * 2, gB + (size_t)r * D + c);
        }
    };

    load_stage(0); cpa_commit();
    load_stage(1); cpa_commit();

    float acc[2][8][4];
    #pragma unroll
    for (int mi = 0; mi < 2; mi++)
        #pragma unroll
        for (int ni = 0; ni < 8; ni++)
            #pragma unroll
            for (int q = 0; q < 4; q++) acc[mi][ni][q] = 0.f;

    // ldmatrix lane address components
    const int a_row = (lane & 7) + ((lane >> 3) & 1) * 8;
    const int a_col = (lane >> 4) * 8;
    const int b_row = (lane & 7) + ((lane >> 4) << 3);
    const int b_col = ((lane >> 3) & 1) * 8;

    for (int ks = 0; ks < NKS; ks++) {
        cpa_wait1();                   // stage ks resident (<=1 group outstanding)
        __syncthreads();               // all warps past iter ks-1: stage (ks+2)%3 free
        if (ks + 2 < NKS) load_stage(ks + 2);
        cpa_commit();                  // unconditional: keeps group count aligned

        const int st = ks % NSTAGE;
        const uint32_t aB = smb + st * (2 * STAGE_B);
        const uint32_t bB = aB + STAGE_B;
        #pragma unroll
        for (int kh = 0; kh < 4; kh++) {
            uint32_t af[2][4];
            uint32_t bf[4][4];
            #pragma unroll
            for (int mi = 0; mi < 2; mi++) {
                uint32_t addr = aB + ((wm * 32 + mi * 16 + a_row) * LDA + kh * 16 + a_col) * 2;
                ldsm_x4(af[mi][0], af[mi][1], af[mi][2], af[mi][3], addr);
            }
            #pragma unroll
            for (int p = 0; p < 4; p++) {
                uint32_t addr = bB + ((wn * 64 + p * 16 + b_row) * LDA + kh * 16 + b_col) * 2;
                ldsm_x4(bf[p][0], bf[p][1], bf[p][2], bf[p][3], addr);
            }
            #pragma unroll
            for (int p = 0; p < 4; p++)
                #pragma unroll
                for (int mi = 0; mi < 2; mi++) {
                    hmma(acc[mi][2 * p + 0], af[mi], bf[p][0], bf[p][1]);
                    hmma(acc[mi][2 * p + 1], af[mi], bf[p][2], bf[p][3]);
                }
        }
    }

    // Epilogue: per-warp (32-row) max per column, staged via smem, coalesced store.
    float* sred2 = (float*)(sm + SMEM_RED);     // [128 b][4 wm]
    __syncthreads();                             // smem stages no longer needed
    #pragma unroll
    for (int ni = 0; ni < 8; ni++) {
        #pragma unroll
        for (int c2 = 0; c2 < 2; c2++) {
            float v = fmaxf(fmaxf(acc[0][ni][c2], acc[0][ni][c2 + 2]),
                            fmaxf(acc[1][ni][c2], acc[1][ni][c2 + 2]));
            v = fmaxf(v, __shfl_xor_sync(0xffffffffu, v, 4));
            v = fmaxf(v, __shfl_xor_sync(0xffffffffu, v, 8));
            v = fmaxf(v, __shfl_xor_sync(0xffffffffu, v, 16));
            if (lane < 4)
                sred2[(wn * 64 + ni * 8 + lane * 2 + c2) * 4 + wm] = v;
        }
    }
    __syncthreads();
    if (tid < BN) {
        float4 v4 = ((const float4*)sred2)[tid];
        *(float4*)(g_submax + (size_t)(b0 + tid) * NSUB + mblk * 4) = v4;
    }
}

// ---------------- phase 2 (fused): select + exact rescore + gather, one CTA per b ----------------
__global__ __launch_bounds__(256) void finalize_kernel(const float* __restrict__ mem,
                                                       float* __restrict__ out) {
    const int b = blockIdx.x;
    const int tid = threadIdx.x;
    const int wid = tid >> 5;
    const int lane = tid & 31;

    __shared__ float ctx_s[D];
    __shared__ float sred[8];
    __shared__ unsigned long long wkey[8];
    __shared__ int clist[256];
    __shared__ int scnt;
    __shared__ unsigned s_idx;

    // stage ctx (fp32, normalized) while scanning submax
    ctx_s[tid]       = g_ctxn[(size_t)b * D + tid];
    ctx_s[tid + 256] = g_ctxn[(size_t)b * D + tid + 256];
    if (tid == 0) scnt = 0;

    // 1) per-b global max over 2048 sub-block maxima (two float4 per thread)
    const float4* row4 = (const float4*)(g_submax + (size_t)b * NSUB);
    float4 v4[2];
    float lmax = -1e38f;
    #pragma unroll
    for (int i = 0; i < 2; i++) {
        v4[i] = row4[tid + 256 * i];
        lmax = fmaxf(lmax, fmaxf(fmaxf(v4[i].x, v4[i].y), fmaxf(v4[i].z, v4[i].w)));
    }
    #pragma unroll
    for (int o = 16; o; o >>= 1) lmax = fmaxf(lmax, __shfl_xor_sync(0xffffffffu, lmax, o));
    if (lane == 0) sred[wid] = lmax;
    __syncthreads();
    float gmax = sred[0];
    #pragma unroll
    for (int w = 1; w < 8; w++) gmax = fmaxf(gmax, sred[w]);
    const float thr = gmax - MARGIN;

    // 2) candidate sub-blocks (typically 1-2)
    #pragma unroll
    for (int i = 0; i < 2; i++) {
        const float vv[4] = { v4[i].x, v4[i].y, v4[i].z, v4[i].w };
        #pragma unroll
        for (int q = 0; q < 4; q++) {
            if (vv[q] >= thr) {
                int p = atomicAdd(&scnt, 1);
                if (p < 256) clist[p] = (tid + 256 * i) * 4 + q;
            }
        }
    }
    __syncthreads();
    const int cnt = (scnt < 256) ? scnt : 256;
    const float4* ctx4 = (const float4*)ctx_s;

    // 3) exact fp32 rescore: 8 warps x 4 rows per 32-row sub-block (MLP-batched loads)
    unsigned long long best = 0ULL;
    for (int ci = 0; ci < cnt; ci++) {
        const int m0 = clist[ci] * 32 + wid * 4;
        float4 mv[4][4];
        #pragma unroll
        for (int r = 0; r < 4; r++) {
            const float4* mrow = (const float4*)(mem + (size_t)(m0 + r) * D);
            #pragma unroll
            for (int j = 0; j < 4; j++) mv[r][j] = mrow[lane + 32 * j];
        }
        #pragma unroll
        for (int r = 0; r < 4; r++) {
            const int mrowi = m0 + r;
            float s = 0.f;
            #pragma unroll
            for (int j = 0; j < 4; j++) {
                float4 cv = ctx4[lane + 32 * j];
                s += mv[r][j].x * cv.x + mv[r][j].y * cv.y
                   + mv[r][j].z * cv.z + mv[r][j].w * cv.w;
            }
            #pragma unroll
            for (int o = 16; o; o >>= 1) s += __shfl_xor_sync(0xffffffffu, s, o);
            float sc = s * g_minv[mrowi];
            unsigned u = __float_as_uint(sc);
            u = (u & 0x80000000u) ? ~u : (u | 0x80000000u);   // order-preserving key
            unsigned long long key = ((unsigned long long)u << 32) | (unsigned)(~mrowi);
            if (key > best) best = key;                        // smallest row wins ties
        }
    }
    if (lane == 0) wkey[wid] = best;
    __syncthreads();
    if (tid == 0) {
        unsigned long long bb = wkey[0];
        #pragma unroll
        for (int w = 1; w < 8; w++) if (wkey[w] > bb) bb = wkey[w];
        s_idx = ~(unsigned)(bb & 0xffffffffull);
    }
    __syncthreads();

    // 4) gather winning row to output
    if (tid < 128) {
        const unsigned idx = s_idx;
        ((float4*)(out + (size_t)b * D))[tid] =
            ((const float4*)(mem + (size_t)idx * D))[tid];
    }
}

// ---------------- launch ----------------
extern "C" void kernel_launch(void* const* d_in, const int* in_sizes, int n_in,
                              void* d_out, int out_size) {
    const float* ctx = (const float*)d_in[0];
    const float* mem = (const float*)d_in[1];
    if (n_in >= 2 && in_sizes[0] > in_sizes[1]) {
        const float* t = ctx; ctx = mem; mem = t;
    }
    float* out = (float*)d_out;

    cudaFuncSetAttribute(score_gemm_kernel,
                         cudaFuncAttributeMaxDynamicSharedMemorySize, SMEM_TOT);

    ctx_prep_kernel<<<NB, 128>>>(ctx);            // also resets arrival counters
    dim3 grid(NB / BN, NM / BM);   // (4, 512): x fastest -> 4 siblings per m-tile adjacent
    score_gemm_kernel<<<grid, 256, SMEM_TOT>>>(mem);
    finalize_kernel<<<NB, 256>>>(mem, out);
}

// round 17
// speedup vs baseline: 1.0790x; 1.0790x over previous
#include <cuda_runtime.h>
#include <cuda_fp16.h>
#include <cstdint>

#define D      512
#define NB     512       // context rows (B)
#define NM     65536     // memory rows (M)
#define BM     128       // m rows per CTA tile
#define BN     128       // b cols per CTA tile
#define BK     64        // k per pipeline stage
#define NSUB   (NM / 32) // 2048 sub-blocks of 32 rows
#define NKS    (D / BK)  // 8 k stages
#define NSTAGE 3
#define LDA    72        // padded smem row stride (elems) -> conflict-free ldmatrix
#define STAGE_E (BM * LDA)            // elems per operand per stage (9216)
#define STAGE_B (STAGE_E * 2)         // bytes (18432)
#define MARGIN 0.0025f   // > 2x (fp16 dot err 2^-10 + fp32 accum err ~3e-5)
#define MEMBLK (NM / 8)  // 8192 mem-prep blocks (8 rows each)

// ---------------- device scratch (no cudaMalloc allowed) ----------------
__device__ float   g_ctxn[NB * D];           // normalized ctx fp32 (exact rescore)
__device__ __half  g_ctxh[NB * D];           // normalized ctx fp16
__device__ __half  g_memh[(size_t)NM * D];   // normalized mem fp16 (64MB)
__device__ float   g_minv[NM];
__device__ float   g_submax[(size_t)NB * NSUB];  // [b][sub] 4MB

// ---------------- fused prep: mem rows (blocks < MEMBLK) + ctx rows (rest) ----------------
__global__ void prep_kernel(const float* __restrict__ mem, const float* __restrict__ ctx) {
    const int tid  = threadIdx.x;
    const int lane = tid & 31;

    if (blockIdx.x < MEMBLK) {
        // ---- mem: inv-norm + normalized fp16 (one warp per row, 8 rows/block) ----
        const int m = blockIdx.x * 8 + (tid >> 5);
        const float4* row = (const float4*)(mem + (size_t)m * D);
        float4 v[4];
        float ss = 0.f;
        #pragma unroll
        for (int i = 0; i < 4; i++) {
            v[i] = row[lane + 32 * i];
            ss += v[i].x * v[i].x + v[i].y * v[i].y + v[i].z * v[i].z + v[i].w * v[i].w;
        }
        #pragma unroll
        for (int o = 16; o; o >>= 1) ss += __shfl_xor_sync(0xffffffffu, ss, o);
        float inv = rsqrtf(fmaxf(ss, 1e-12f));
        if (lane == 0) g_minv[m] = inv;
        #pragma unroll
        for (int i = 0; i < 4; i++) {
            __half2 p0 = __floats2half2_rn(v[i].x * inv, v[i].y * inv);
            __half2 p1 = __floats2half2_rn(v[i].z * inv, v[i].w * inv);
            uint2 u = make_uint2(*(uint32_t*)&p0, *(uint32_t*)&p1);
            *(uint2*)(g_memh + (size_t)m * D + 4 * (lane + 32 * i)) = u;
        }
    } else {
        // ---- ctx: normalize -> fp32 + fp16 (2 rows/block, 128 threads each) ----
        const int half = tid >> 7;                 // 0 or 1
        const int t    = tid & 127;                // thread within row
        const int b    = (blockIdx.x - MEMBLK) * 2 + half;
        __shared__ float ws[2][4];
        float4 v = ((const float4*)(ctx + (size_t)b * D))[t];
        float ss = v.x * v.x + v.y * v.y + v.z * v.z + v.w * v.w;
        #pragma unroll
        for (int o = 16; o; o >>= 1) ss += __shfl_xor_sync(0xffffffffu, ss, o);
        if (lane == 0) ws[half][(t >> 5)] = ss;
        __syncthreads();
        float sc = rsqrtf(fmaxf(ws[half][0] + ws[half][1] + ws[half][2] + ws[half][3], 1e-12f));
        float4 n4 = make_float4(v.x * sc, v.y * sc, v.z * sc, v.w * sc);
        ((float4*)(g_ctxn + (size_t)b * D))[t] = n4;
        __half2 p0 = __floats2half2_rn(n4.x, n4.y);
        __half2 p1 = __floats2half2_rn(n4.z, n4.w);
        uint2 u = make_uint2(*(uint32_t*)&p0, *(uint32_t*)&p1);
        *(uint2*)(g_ctxh + (size_t)b * D + 4 * t) = u;
    }
}

// ---------------- asm helpers ----------------
__device__ __forceinline__ uint32_t smem_u32(const void* p) {
    uint32_t a;
    asm("{ .reg .u64 t; cvta.to.shared.u64 t, %1; cvt.u32.u64 %0, t; }" : "=r"(a) : "l"(p));
    return a;
}
__device__ __forceinline__ void cpa16(uint32_t dst, const void* src) {
    asm volatile("cp.async.cg.shared.global [%0], [%1], 16;" :: "r"(dst), "l"(src));
}
__device__ __forceinline__ void cpa_commit() {
    asm volatile("cp.async.commit_group;");
}
__device__ __forceinline__ void cpa_wait1() {
    asm volatile("cp.async.wait_group 1;");
}
__device__ __forceinline__ void ldsm_x4(uint32_t& r0, uint32_t& r1, uint32_t& r2, uint32_t& r3,
                                        uint32_t addr) {
    asm volatile("ldmatrix.sync.aligned.m8n8.x4.shared.b16 {%0,%1,%2,%3}, [%4];"
                 : "=r"(r0), "=r"(r1), "=r"(r2), "=r"(r3) : "r"(addr));
}
__device__ __forceinline__ void hmma(float* c, const uint32_t* a, uint32_t b0, uint32_t b1) {
    asm volatile(
        "mma.sync.aligned.m16n8k16.row.col.f32.f16.f16.f32 "
        "{%0,%1,%2,%3}, {%4,%5,%6,%7}, {%8,%9}, {%0,%1,%2,%3};"
        : "+f"(c[0]), "+f"(c[1]), "+f"(c[2]), "+f"(c[3])
        : "r"(a[0]), "r"(a[1]), "r"(a[2]), "r"(a[3]), "r"(b0), "r"(b1));
}

// ---------------- phase 1: fp16 GEMM + per-(b, 32-row-sub) max ----------------
// CTA: 128 m x 128 b, 256 threads (8 warps: 4 m-warps (wm) x 2 n-warps (wn)).
// Warp tile 32(m) x 64(n). BK=64 -> 4 kh per stage, 3-stage cp.async pipeline.
// (Round-10 proven configuration, unchanged.)
#define SMEM_RED (NSTAGE * 2 * STAGE_B)        // 110592: after 3 stages of A+B
#define SMEM_TOT (SMEM_RED + BN * 4 * 4)       // + sred2[128][4] floats = 112640

__global__ __launch_bounds__(256, 2) void score_gemm_kernel() {
    extern __shared__ char sm[];
    const uint32_t smb = smem_u32(sm);
    const int tid  = threadIdx.x;
    const int lane = tid & 31;
    const int wid  = tid >> 5;
    const int wm   = wid & 3;
    const int wn   = wid >> 2;
    const int b0   = blockIdx.x * BN;
    const int mblk = blockIdx.y;
    const int m0   = mblk * BM;

    auto load_stage = [&](int ks) {
        const int st = ks % NSTAGE;
        const uint32_t aB = smb + st * (2 * STAGE_B);
        const uint32_t bB = aB + STAGE_B;
        const __half* gA = g_memh + (size_t)m0 * D + ks * BK;
        const __half* gB = g_ctxh + (size_t)b0 * D + ks * BK;
        #pragma unroll
        for (int it = 0; it < 4; it++) {
            int f = tid + it * 256;
            int r = f >> 3, c = (f & 7) << 3;
            cpa16(aB + (r * LDA + c) * 2, gA + (size_t)r * D + c);
            cpa16(bB + (r * LDA + c) * 2, gB + (size_t)r * D + c);
        }
    };

    load_stage(0); cpa_commit();
    load_stage(1); cpa_commit();

    float acc[2][8][4];
    #pragma unroll
    for (int mi = 0; mi < 2; mi++)
        #pragma unroll
        for (int ni = 0; ni < 8; ni++)
            #pragma unroll
            for (int q = 0; q < 4; q++) acc[mi][ni][q] = 0.f;

    // ldmatrix lane address components
    const int a_row = (lane & 7) + ((lane >> 3) & 1) * 8;
    const int a_col = (lane >> 4) * 8;
    const int b_row = (lane & 7) + ((lane >> 4) << 3);
    const int b_col = ((lane >> 3) & 1) * 8;

    for (int ks = 0; ks < NKS; ks++) {
        cpa_wait1();                   // stage ks resident (<=1 group outstanding)
        __syncthreads();               // all warps past iter ks-1: stage (ks+2)%3 free
        if (ks + 2 < NKS) load_stage(ks + 2);
        cpa_commit();                  // unconditional: keeps group count aligned

        const int st = ks % NSTAGE;
        const uint32_t aB = smb + st * (2 * STAGE_B);
        const uint32_t bB = aB + STAGE_B;
        #pragma unroll
        for (int kh = 0; kh < 4; kh++) {
            uint32_t af[2][4];
            uint32_t bf[4][4];
            #pragma unroll
            for (int mi = 0; mi < 2; mi++) {
                uint32_t addr = aB + ((wm * 32 + mi * 16 + a_row) * LDA + kh * 16 + a_col) * 2;
                ldsm_x4(af[mi][0], af[mi][1], af[mi][2], af[mi][3], addr);
            }
            #pragma unroll
            for (int p = 0; p < 4; p++) {
                uint32_t addr = bB + ((wn * 64 + p * 16 + b_row) * LDA + kh * 16 + b_col) * 2;
                ldsm_x4(bf[p][0], bf[p][1], bf[p][2], bf[p][3], addr);
            }
            #pragma unroll
            for (int p = 0; p < 4; p++)
                #pragma unroll
                for (int mi = 0; mi < 2; mi++) {
                    hmma(acc[mi][2 * p + 0], af[mi], bf[p][0], bf[p][1]);
                    hmma(acc[mi][2 * p + 1], af[mi], bf[p][2], bf[p][3]);
                }
        }
    }

    // Epilogue: per-warp (32-row) max per column, staged via smem, coalesced store.
    float* sred2 = (float*)(sm + SMEM_RED);     // [128 b][4 wm]
    __syncthreads();                             // smem stages no longer needed
    #pragma unroll
    for (int ni = 0; ni < 8; ni++) {
        #pragma unroll
        for (int c2 = 0; c2 < 2; c2++) {
            float v = fmaxf(fmaxf(acc[0][ni][c2], acc[0][ni][c2 + 2]),
                            fmaxf(acc[1][ni][c2], acc[1][ni][c2 + 2]));
            v = fmaxf(v, __shfl_xor_sync(0xffffffffu, v, 4));
            v = fmaxf(v, __shfl_xor_sync(0xffffffffu, v, 8));
            v = fmaxf(v, __shfl_xor_sync(0xffffffffu, v, 16));
            if (lane < 4)
                sred2[(wn * 64 + ni * 8 + lane * 2 + c2) * 4 + wm] = v;
        }
    }
    __syncthreads();
    if (tid < BN) {
        float4 v4 = ((const float4*)sred2)[tid];
        *(float4*)(g_submax + (size_t)(b0 + tid) * NSUB + mblk * 4) = v4;
    }
}

// ---------------- phase 2 (fused): select + exact rescore + gather, one CTA per b ----------------
__global__ __launch_bounds__(256) void finalize_kernel(const float* __restrict__ mem,
                                                       float* __restrict__ out) {
    const int b = blockIdx.x;
    const int tid = threadIdx.x;
    const int wid = tid >> 5;
    const int lane = tid & 31;

    __shared__ float ctx_s[D];
    __shared__ float sred[8];
    __shared__ unsigned long long wkey[8];
    __shared__ int clist[256];
    __shared__ int scnt;
    __shared__ unsigned s_idx;

    // stage ctx (fp32, normalized) while scanning submax
    ctx_s[tid]       = g_ctxn[(size_t)b * D + tid];
    ctx_s[tid + 256] = g_ctxn[(size_t)b * D + tid + 256];
    if (tid == 0) scnt = 0;

    // 1) per-b global max over 2048 sub-block maxima (two float4 per thread)
    const float4* row4 = (const float4*)(g_submax + (size_t)b * NSUB);
    float4 v4[2];
    float lmax = -1e38f;
    #pragma unroll
    for (int i = 0; i < 2; i++) {
        v4[i] = row4[tid + 256 * i];
        lmax = fmaxf(lmax, fmaxf(fmaxf(v4[i].x, v4[i].y), fmaxf(v4[i].z, v4[i].w)));
    }
    #pragma unroll
    for (int o = 16; o; o >>= 1) lmax = fmaxf(lmax, __shfl_xor_sync(0xffffffffu, lmax, o));
    if (lane == 0) sred[wid] = lmax;
    __syncthreads();
    float gmax = sred[0];
    #pragma unroll
    for (int w = 1; w < 8; w++) gmax = fmaxf(gmax, sred[w]);
    const float thr = gmax - MARGIN;

    // 2) candidate sub-blocks (typically 1-2)
    #pragma unroll
    for (int i = 0; i < 2; i++) {
        const float vv[4] = { v4[i].x, v4[i].y, v4[i].z, v4[i].w };
        #pragma unroll
        for (int q = 0; q < 4; q++) {
            if (vv[q] >= thr) {
                int p = atomicAdd(&scnt, 1);
                if (p < 256) clist[p] = (tid + 256 * i) * 4 + q;
            }
        }
    }
    __syncthreads();
    const int cnt = (scnt < 256) ? scnt : 256;
    const float4* ctx4 = (const float4*)ctx_s;

    // 3) exact fp32 rescore: 8 warps x 4 rows per 32-row sub-block (MLP-batched loads)
    unsigned long long best = 0ULL;
    for (int ci = 0; ci < cnt; ci++) {
        const int m0 = clist[ci] * 32 + wid * 4;
        float4 mv[4][4];
        #pragma unroll
        for (int r = 0; r < 4; r++) {
            const float4* mrow = (const float4*)(mem + (size_t)(m0 + r) * D);
            #pragma unroll
            for (int j = 0; j < 4; j++) mv[r][j] = mrow[lane + 32 * j];
        }
        #pragma unroll
        for (int r = 0; r < 4; r++) {
            const int mrowi = m0 + r;
            float s = 0.f;
            #pragma unroll
            for (int j = 0; j < 4; j++) {
                float4 cv = ctx4[lane + 32 * j];
                s += mv[r][j].x * cv.x + mv[r][j].y * cv.y
                   + mv[r][j].z * cv.z + mv[r][j].w * cv.w;
            }
            #pragma unroll
            for (int o = 16; o; o >>= 1) s += __shfl_xor_sync(0xffffffffu, s, o);
            float sc = s * g_minv[mrowi];
            unsigned u = __float_as_uint(sc);
            u = (u & 0x80000000u) ? ~u : (u | 0x80000000u);   // order-preserving key
            unsigned long long key = ((unsigned long long)u << 32) | (unsigned)(~mrowi);
            if (key > best) best = key;                        // smallest row wins ties
        }
    }
    if (lane == 0) wkey[wid] = best;
    __syncthreads();
    if (tid == 0) {
        unsigned long long bb = wkey[0];
        #pragma unroll
        for (int w = 1; w < 8; w++) if (wkey[w] > bb) bb = wkey[w];
        s_idx = ~(unsigned)(bb & 0xffffffffull);
    }
    __syncthreads();

    // 4) gather winning row to output
    if (tid < 128) {
        const unsigned idx = s_idx;
        ((float4*)(out + (size_t)b * D))[tid] =
            ((const float4*)(mem + (size_t)idx * D))[tid];
    }
}

// ---------------- launch ----------------
extern "C" void kernel_launch(void* const* d_in, const int* in_sizes, int n_in,
                              void* d_out, int out_size) {
    const float* ctx = (const float*)d_in[0];
    const float* mem = (const float*)d_in[1];
    if (n_in >= 2 && in_sizes[0] > in_sizes[1]) {
        const float* t = ctx; ctx = mem; mem = t;
    }
    float* out = (float*)d_out;

    cudaFuncSetAttribute(score_gemm_kernel,
                         cudaFuncAttributeMaxDynamicSharedMemorySize, SMEM_TOT);

    prep_kernel<<<MEMBLK + NB / 2, 256>>>(mem, ctx);   // fused mem+ctx prep
    dim3 grid(NB / BN, NM / BM);   // (4, 512): b fastest -> mem tiles shared in L2
    score_gemm_kernel<<<grid, 256, SMEM_TOT>>>();
    finalize_kernel<<<NB, 256>>>(mem, out);
}